// round 6
// baseline (speedup 1.0000x reference)
#include <cuda_runtime.h>
#include <cstdint>

#define N_NODES 2048
#define N_ATTRS 64
#define TOPK    8

// Feature-major sorted streams: g_xs[f * N_NODES + r] = (value, node index) of
// the r-th largest x[:, f]. All 32 lanes of a warp share one stream (uniform
// loads). +16 float2 tail pad so the 8-deep software-pipelined prefetch never
// reads out of bounds.
__device__ __align__(16) float2 g_xs[(size_t)N_ATTRS * N_NODES + 16];

// ---------------------------------------------------------------------------
// Kernel 1: per-feature bitonic sort of (x value, node index), descending.
// One block per feature; 2048 elements in smem; 512 threads.
// ---------------------------------------------------------------------------
__global__ void __launch_bounds__(512) sort_kernel(const float* __restrict__ x) {
    __shared__ float sval[N_NODES];
    __shared__ int   sidx[N_NODES];
    const int f = blockIdx.x;

    for (int i = threadIdx.x; i < N_NODES; i += blockDim.x) {
        sval[i] = x[(size_t)i * N_ATTRS + f];
        sidx[i] = i;
    }
    __syncthreads();

    for (int size = 2; size <= N_NODES; size <<= 1) {
        for (int stride = size >> 1; stride > 0; stride >>= 1) {
            for (int i = threadIdx.x; i < N_NODES; i += blockDim.x) {
                int j = i ^ stride;
                if (j > i) {
                    bool desc = ((i & size) == 0);  // final pass: all descending
                    float vi = sval[i], vj = sval[j];
                    bool sw = desc ? (vi < vj) : (vi > vj);
                    if (sw) {
                        sval[i] = vj; sval[j] = vi;
                        int t = sidx[i]; sidx[i] = sidx[j]; sidx[j] = t;
                    }
                }
            }
            __syncthreads();
        }
    }

    float2* __restrict__ dst = g_xs + (size_t)f * N_NODES;
    for (int r = threadIdx.x; r < N_NODES; r += blockDim.x)
        dst[r] = make_float2(sval[r], __int_as_float(sidx[r]));
}

// ---------------------------------------------------------------------------
// Kernel 2: warp-cooperative pruned top-8.
//
// Warp = 32 consecutive destination nodes (lanes) x one feature. Lanes share
// the feature's descending-x candidate stream (uniform loads). The gather at
// candidate i is adj[i][jbase..jbase+31]: one aligned 128-byte line per
// candidate, directly from the input layout -> no transpose, no smem tiles.
// A block is 8 warps = 8 consecutive features of the SAME 32-node group, so
// outputs are staged in smem and written as 32B-contiguous vector stores.
//
// Exactness:
//  - adj in [0,1] => rn(a*x) <= max(x,0) =: ub (rounding is monotone), and ub
//    is non-increasing along the sorted stream. When every lane's m7 >= ub,
//    no remaining candidate can alter any lane's top-8 -> warp break exact.
//  - A lane already satisfying m7 >= ub keeps scanning harmlessly: all its
//    future products are <= ub <= m7, so insert8 is a no-op.
//  - Chunk-max filter: if max(v0..v7) <= m7 for a lane, skipping its inserts
//    is exact; insert order within a chunk never changes the value multiset.
// ---------------------------------------------------------------------------
__device__ __forceinline__ void insert8(float v,
    float& m0, float& m1, float& m2, float& m3,
    float& m4, float& m5, float& m6, float& m7) {
    if (v > m7) {
        m7 = v;
        float t;
        if (m7 > m6) { t = m6; m6 = m7; m7 = t; }
        if (m6 > m5) { t = m5; m5 = m6; m6 = t; }
        if (m5 > m4) { t = m4; m4 = m5; m5 = t; }
        if (m4 > m3) { t = m3; m3 = m4; m4 = t; }
        if (m3 > m2) { t = m2; m2 = m3; m3 = t; }
        if (m2 > m1) { t = m1; m1 = m2; m2 = t; }
        if (m1 > m0) { t = m0; m0 = m1; m1 = t; }
    }
}

#define WARPS_PER_BLOCK 8   // must divide 64 so a block never straddles node groups

__global__ void __launch_bounds__(32 * WARPS_PER_BLOCK)
topk_kernel(const float* __restrict__ x,
            const float* __restrict__ adj,
            float* __restrict__ out) {
    // Staging tile: [node][slot s][feature-in-block]. 9216 B.
    __shared__ float sout[32][TOPK + 1][WARPS_PER_BLOCK];

    const int tid   = threadIdx.x;
    const int lane  = tid & 31;
    const int w     = tid >> 5;                                   // warp in block
    const int W     = blockIdx.x * WARPS_PER_BLOCK + w;           // global warp id
    const int f     = W & (N_ATTRS - 1);
    const int jbase = (W >> 6) * 32;                              // 64 features per node group
    const int jcol  = jbase + lane;

    const float2* __restrict__ xs = g_xs + (size_t)f * N_NODES;

    const float NEG_INF = __int_as_float(0xff800000);
    float m0 = NEG_INF, m1 = NEG_INF, m2 = NEG_INF, m3 = NEG_INF;
    float m4 = NEG_INF, m5 = NEG_INF, m6 = NEG_INF, m7 = NEG_INF;

    // 8-candidate chunks, 1-deep software pipeline on the uniform stream loads
    // (takes the xs fetch off the dependent xs -> idx -> gather critical path).
    float4 a = *(const float4*)(xs);        // candidates r+0, r+1
    float4 b = *(const float4*)(xs + 2);    // r+2, r+3
    float4 c = *(const float4*)(xs + 4);    // r+4, r+5
    float4 d = *(const float4*)(xs + 6);    // r+6, r+7

    for (int r = 0; r < N_NODES; r += 8) {
        float4 an = *(const float4*)(xs + r + 8);
        float4 bn = *(const float4*)(xs + r + 10);
        float4 cn = *(const float4*)(xs + r + 12);
        float4 dn = *(const float4*)(xs + r + 14);

        // ub non-increasing; exit when no lane can still improve.
        if (__all_sync(0xffffffffu, m7 >= fmaxf(a.x, 0.0f))) break;

        // Eight independent gathers, one 128B line each, coalesced across lanes.
        float w0 = adj[(size_t)__float_as_int(a.y) * N_NODES + jcol];
        float w1 = adj[(size_t)__float_as_int(a.w) * N_NODES + jcol];
        float w2 = adj[(size_t)__float_as_int(b.y) * N_NODES + jcol];
        float w3 = adj[(size_t)__float_as_int(b.w) * N_NODES + jcol];
        float w4 = adj[(size_t)__float_as_int(c.y) * N_NODES + jcol];
        float w5 = adj[(size_t)__float_as_int(c.w) * N_NODES + jcol];
        float w6 = adj[(size_t)__float_as_int(d.y) * N_NODES + jcol];
        float w7 = adj[(size_t)__float_as_int(d.w) * N_NODES + jcol];

        float v0 = w0 * a.x, v1 = w1 * a.z;
        float v2 = w2 * b.x, v3 = w3 * b.z;
        float v4 = w4 * c.x, v5 = w5 * c.z;
        float v6 = w6 * d.x, v7 = w7 * d.z;

        float cmax = fmaxf(fmaxf(fmaxf(v0, v1), fmaxf(v2, v3)),
                           fmaxf(fmaxf(v4, v5), fmaxf(v6, v7)));
        if (cmax > m7) {
            insert8(v0, m0, m1, m2, m3, m4, m5, m6, m7);
            insert8(v1, m0, m1, m2, m3, m4, m5, m6, m7);
            insert8(v2, m0, m1, m2, m3, m4, m5, m6, m7);
            insert8(v3, m0, m1, m2, m3, m4, m5, m6, m7);
            insert8(v4, m0, m1, m2, m3, m4, m5, m6, m7);
            insert8(v5, m0, m1, m2, m3, m4, m5, m6, m7);
            insert8(v6, m0, m1, m2, m3, m4, m5, m6, m7);
            insert8(v7, m0, m1, m2, m3, m4, m5, m6, m7);
        }

        a = an; b = bn; c = cn; d = dn;
    }

    // Stage results: sout[node][s][feature-in-block].
    sout[lane][0][w] = x[(size_t)jcol * N_ATTRS + f];
    sout[lane][1][w] = m0;
    sout[lane][2][w] = m1;
    sout[lane][3][w] = m2;
    sout[lane][4][w] = m3;
    sout[lane][5][w] = m4;
    sout[lane][6][w] = m5;
    sout[lane][7][w] = m6;
    sout[lane][8][w] = m7;
    __syncthreads();

    // Coalesced writeback: each (node, s) pair is 8 consecutive features =
    // 32 contiguous bytes in out. 288 pairs, 256 threads.
    const int fbase = (blockIdx.x * WARPS_PER_BLOCK) & (N_ATTRS - 1);
    for (int p = tid; p < 32 * (TOPK + 1); p += 32 * WARPS_PER_BLOCK) {
        int jl = p / (TOPK + 1);
        int s  = p % (TOPK + 1);
        float4 lo = *(const float4*)&sout[jl][s][0];
        float4 hi = *(const float4*)&sout[jl][s][4];
        float* o = out + (size_t)(jbase + jl) * (TOPK + 1) * N_ATTRS + s * N_ATTRS + fbase;
        *(float4*)(o)     = lo;
        *(float4*)(o + 4) = hi;
    }
}

// ---------------------------------------------------------------------------
extern "C" void kernel_launch(void* const* d_in, const int* in_sizes, int n_in,
                              void* d_out, int out_size) {
    const float* x   = (const float*)d_in[0];   // (2048, 64) f32
    const float* adj = (const float*)d_in[1];   // (2048, 2048) f32
    float* out = (float*)d_out;                 // (2048, 9, 64) f32

    sort_kernel<<<N_ATTRS, 512>>>(x);

    // 2048/32 node groups x 64 features = 4096 warps = 512 blocks of 8 warps.
    const int n_warps  = (N_NODES / 32) * N_ATTRS;
    const int n_blocks = n_warps / WARPS_PER_BLOCK;
    topk_kernel<<<n_blocks, 32 * WARPS_PER_BLOCK>>>(x, adj, out);
}

// round 11
// speedup vs baseline: 1.2050x; 1.2050x over previous
#include <cuda_runtime.h>
#include <cstdint>

#define N_NODES 2048
#define N_ATTRS 64
#define TOPK    8

// Feature-major sorted streams: g_xs[f * N_NODES + r] = (value, node index) of
// the r-th largest x[:, f]. All 32 lanes of a warp share one stream (uniform
// loads). +16 float2 tail pad: the pipelined prefetch reads at most rank 2063.
__device__ __align__(16) float2 g_xs[(size_t)N_ATTRS * N_NODES + 16];

// ---------------------------------------------------------------------------
// Kernel 1: per-feature bitonic sort of (x value, node index), descending.
// One block per feature; 1024 threads = one comparator per thread per pass,
// so each of the 66 network passes is a single smem round-trip + barrier.
// ---------------------------------------------------------------------------
__global__ void __launch_bounds__(1024) sort_kernel(const float* __restrict__ x) {
    __shared__ float sval[N_NODES];
    __shared__ int   sidx[N_NODES];
    const int f = blockIdx.x;
    const int t = threadIdx.x;

    for (int i = t; i < N_NODES; i += 1024) {
        sval[i] = x[(size_t)i * N_ATTRS + f];
        sidx[i] = i;
    }
    __syncthreads();

    for (int size = 2; size <= N_NODES; size <<= 1) {
        for (int stride = size >> 1; stride > 0; stride >>= 1) {
            // Comparator t handles pair (i, j), identical network to the
            // reference loop formulation (j = i ^ stride, j > i).
            int i = ((t & ~(stride - 1)) << 1) | (t & (stride - 1));
            int j = i | stride;
            bool desc = ((i & size) == 0);  // final size=2048 pass: descending
            float vi = sval[i], vj = sval[j];
            if (desc ? (vi < vj) : (vi > vj)) {
                sval[i] = vj; sval[j] = vi;
                int tmp = sidx[i]; sidx[i] = sidx[j]; sidx[j] = tmp;
            }
            __syncthreads();
        }
    }

    float2* __restrict__ dst = g_xs + (size_t)f * N_NODES;
    for (int r = t; r < N_NODES; r += 1024)
        dst[r] = make_float2(sval[r], __int_as_float(sidx[r]));
}

// ---------------------------------------------------------------------------
// Kernel 2: warp-pair-cooperative pruned top-8.
//
// Each (32-node group, feature) task is handled by TWO warps: warp h scans
// chunks [16k+8h, 16k+8h+8) of the feature's descending-x candidate stream
// (both subsequences are descending, so pruning stays exact per half), then
// the pair merges: top-8 of (top-8 evens  U  top-8 odds) = top-8 of all.
// 8192 warps total (occupancy ~86% vs 43% ceiling of the unsplit mapping).
//
// The gather at candidate i is adj[i][jbase..jbase+31]: one aligned 128-byte
// line per candidate, coalesced, each line read by exactly one warp of the
// pair. Block = 8 warps = 4 features x 2 halves of one node group; outputs
// staged in smem, written as 16B contiguous vector stores.
//
// Exactness:
//  - adj in [0,1] => rn(a*x) <= max(x,0) =: ub (rounding monotone); ub is
//    non-increasing along each half-stream. When every lane's m7 >= ub at the
//    chunk head, no remaining candidate in that half can enter -> break exact.
//  - Chunk-max filter: if max(v0..v7) <= m7 for a lane, skipping its inserts
//    is exact; insert order never changes the value multiset.
//  - Pair merge: inserting the odd-half's 8 values into the even-half's
//    sorted 8 yields the top-8 of the 16-value union.
// ---------------------------------------------------------------------------
__device__ __forceinline__ void insert8(float v,
    float& m0, float& m1, float& m2, float& m3,
    float& m4, float& m5, float& m6, float& m7) {
    if (v > m7) {
        m7 = v;
        float t;
        if (m7 > m6) { t = m6; m6 = m7; m7 = t; }
        if (m6 > m5) { t = m5; m5 = m6; m6 = t; }
        if (m5 > m4) { t = m4; m4 = m5; m5 = t; }
        if (m4 > m3) { t = m3; m3 = m4; m4 = t; }
        if (m3 > m2) { t = m2; m2 = m3; m3 = t; }
        if (m2 > m1) { t = m1; m1 = m2; m2 = t; }
        if (m1 > m0) { t = m0; m0 = m1; m1 = t; }
    }
}

#define WPB 8   // 8 warps = 4 features x 2 stream-halves

__global__ void __launch_bounds__(32 * WPB)
topk_kernel(const float* __restrict__ x,
            const float* __restrict__ adj,
            float* __restrict__ out) {
    // Pair-merge buffer: [feature-in-block][node][half*8 + slot], padded to 17
    // floats per row so lane-stride-17 stores are bank-conflict-free.
    __shared__ float smrg[4][32][17];
    // Staging tile for coalesced writeback: [node][slot s][feature-in-block].
    __shared__ float sout[32][TOPK + 1][4];

    const int tid   = threadIdx.x;
    const int lane  = tid & 31;
    const int w     = tid >> 5;          // 0..7
    const int fq    = w >> 1;            // feature within block: 0..3
    const int h     = w & 1;             // stream half: even/odd chunks

    const int g     = blockIdx.x >> 4;          // node group 0..63
    const int fbase = (blockIdx.x & 15) * 4;    // 16 blocks per group
    const int f     = fbase + fq;
    const int jbase = g * 32;
    const int jcol  = jbase + lane;

    const float2* __restrict__ xs = g_xs + (size_t)f * N_NODES;

    const float NEG_INF = __int_as_float(0xff800000);
    float m0 = NEG_INF, m1 = NEG_INF, m2 = NEG_INF, m3 = NEG_INF;
    float m4 = NEG_INF, m5 = NEG_INF, m6 = NEG_INF, m7 = NEG_INF;

    // 8-candidate chunks at stride 16 (alternating halves), 1-deep software
    // pipeline on the uniform stream loads.
    float4 a = *(const float4*)(xs + 8 * h);
    float4 b = *(const float4*)(xs + 8 * h + 2);
    float4 c = *(const float4*)(xs + 8 * h + 4);
    float4 d = *(const float4*)(xs + 8 * h + 6);

    for (int rb = 8 * h; rb < N_NODES; rb += 16) {
        float4 an = *(const float4*)(xs + rb + 16);
        float4 bn = *(const float4*)(xs + rb + 18);
        float4 cn = *(const float4*)(xs + rb + 20);
        float4 dn = *(const float4*)(xs + rb + 22);

        // ub non-increasing along this half; exit when no lane can improve.
        if (__all_sync(0xffffffffu, m7 >= fmaxf(a.x, 0.0f))) break;

        // Eight independent gathers, one 128B line each, coalesced across lanes.
        float w0 = adj[(size_t)__float_as_int(a.y) * N_NODES + jcol];
        float w1 = adj[(size_t)__float_as_int(a.w) * N_NODES + jcol];
        float w2 = adj[(size_t)__float_as_int(b.y) * N_NODES + jcol];
        float w3 = adj[(size_t)__float_as_int(b.w) * N_NODES + jcol];
        float w4 = adj[(size_t)__float_as_int(c.y) * N_NODES + jcol];
        float w5 = adj[(size_t)__float_as_int(c.w) * N_NODES + jcol];
        float w6 = adj[(size_t)__float_as_int(d.y) * N_NODES + jcol];
        float w7 = adj[(size_t)__float_as_int(d.w) * N_NODES + jcol];

        float v0 = w0 * a.x, v1 = w1 * a.z;
        float v2 = w2 * b.x, v3 = w3 * b.z;
        float v4 = w4 * c.x, v5 = w5 * c.z;
        float v6 = w6 * d.x, v7 = w7 * d.z;

        float cmax = fmaxf(fmaxf(fmaxf(v0, v1), fmaxf(v2, v3)),
                           fmaxf(fmaxf(v4, v5), fmaxf(v6, v7)));
        if (cmax > m7) {
            insert8(v0, m0, m1, m2, m3, m4, m5, m6, m7);
            insert8(v1, m0, m1, m2, m3, m4, m5, m6, m7);
            insert8(v2, m0, m1, m2, m3, m4, m5, m6, m7);
            insert8(v3, m0, m1, m2, m3, m4, m5, m6, m7);
            insert8(v4, m0, m1, m2, m3, m4, m5, m6, m7);
            insert8(v5, m0, m1, m2, m3, m4, m5, m6, m7);
            insert8(v6, m0, m1, m2, m3, m4, m5, m6, m7);
            insert8(v7, m0, m1, m2, m3, m4, m5, m6, m7);
        }

        a = an; b = bn; c = cn; d = dn;
    }

    // Publish this half's sorted top-8.
    float* mrow = &smrg[fq][lane][h * 8];
    mrow[0] = m0; mrow[1] = m1; mrow[2] = m2; mrow[3] = m3;
    mrow[4] = m4; mrow[5] = m5; mrow[6] = m6; mrow[7] = m7;
    __syncthreads();

    // Even-half warp merges the odd half's 8 values and stages the result.
    if (h == 0) {
        const float* other = &smrg[fq][lane][8];
#pragma unroll
        for (int s = 0; s < 8; ++s)
            insert8(other[s], m0, m1, m2, m3, m4, m5, m6, m7);

        sout[lane][0][fq] = x[(size_t)jcol * N_ATTRS + f];
        sout[lane][1][fq] = m0;
        sout[lane][2][fq] = m1;
        sout[lane][3][fq] = m2;
        sout[lane][4][fq] = m3;
        sout[lane][5][fq] = m4;
        sout[lane][6][fq] = m5;
        sout[lane][7][fq] = m6;
        sout[lane][8][fq] = m7;
    }
    __syncthreads();

    // Coalesced writeback: each (node, s) pair is 4 consecutive features =
    // 16 contiguous bytes in out. 288 pairs, 256 threads.
    for (int p = tid; p < 32 * (TOPK + 1); p += 32 * WPB) {
        int jl = p / (TOPK + 1);
        int s  = p % (TOPK + 1);
        float4 v = *(const float4*)&sout[jl][s][0];
        float* o = out + (size_t)(jbase + jl) * (TOPK + 1) * N_ATTRS + s * N_ATTRS + fbase;
        *(float4*)(o) = v;
    }
}

// ---------------------------------------------------------------------------
extern "C" void kernel_launch(void* const* d_in, const int* in_sizes, int n_in,
                              void* d_out, int out_size) {
    const float* x   = (const float*)d_in[0];   // (2048, 64) f32
    const float* adj = (const float*)d_in[1];   // (2048, 2048) f32
    float* out = (float*)d_out;                 // (2048, 9, 64) f32

    sort_kernel<<<N_ATTRS, 1024>>>(x);

    // 64 node groups x 16 blocks (4 features x 2 halves each) = 1024 blocks.
    topk_kernel<<<1024, 32 * WPB>>>(x, adj, out);
}